// round 15
// baseline (speedup 1.0000x reference)
#include <cuda_runtime.h>
#include <cuda_fp16.h>
#include <cstdint>
#include <cstddef>

#define N_NODES 100000
#define N_EDGES 1600000
#define IN_DIM  256
#define OUT_DIM 128

// ---------------- scratch (no cudaMalloc allowed) ----------------
__device__ __half g_h16[(size_t)N_NODES * OUT_DIM]; // h (unscaled, fp16)  (25.6 MB)
__device__ uint32_t g_wcf[16384];                   // Wc fp16 pairs, [ch64][n][kloc64]
__device__ float g_dinv[N_NODES];                   // 1/sqrt(deg)
__device__ int   g_cnt[N_NODES];                    // in-degree (edges only)
__device__ int   g_cur[N_NODES];                    // scatter cursors
__device__ int   g_rowptr[N_NODES + 1];             // CSR row pointers (by target)
__device__ int   g_srcs[N_EDGES];                   // sorted-by-target source ids
__device__ int   g_incl[N_NODES];                   // per-chunk inclusive scans
__device__ int   g_bsum[512];                       // block sums for scan
__device__ int   g_is64;                            // edge_index dtype flag

__device__ __forceinline__ uint32_t smem_u32(const void* p) {
    uint32_t a;
    asm("{ .reg .u64 t; cvta.to.shared.u64 t, %1; cvt.u32.u64 %0, t; }" : "=r"(a) : "l"(p));
    return a;
}

__device__ __forceinline__ uint32_t h2_bits(__half2 h) {
    return *reinterpret_cast<uint32_t*>(&h);
}

__device__ __forceinline__ void cp16(uint32_t dst, const void* src, bool pred) {
    int sz = pred ? 16 : 0;
    asm volatile("cp.async.ca.shared.global [%0], [%1], 16, %2;"
                 :: "r"(dst), "l"(src), "r"(sz) : "memory");
}

// ---------------- dtype detection (int64 vs int32 edge_index) ----------------
__global__ void detect_kernel(const void* __restrict__ ei) {
    if (threadIdx.x == 0 && blockIdx.x == 0) {
        const long long* p = (const long long*)ei;
        int is64 = 1;
        for (int i = 0; i < 8; i++) {
            long long v = p[i];
            if (v < 0 || v >= N_NODES) { is64 = 0; break; }
        }
        g_is64 = is64;
    }
}

__device__ __forceinline__ int load_idx(const void* __restrict__ ei, long long i, int is64) {
    if (is64) return (int)((const long long*)ei)[i];
    return ((const int*)ei)[i];
}

// ---------------- Wc = Wg @ Wp, converted to fp16 ----------------
// layout (half view): [ch64][n][kloc]  ch = k>>6, kloc = k&63
__global__ void wc_kernel(const float* __restrict__ Wp, const float* __restrict__ Wg) {
    __shared__ float sWg[OUT_DIM];
    const int o2 = blockIdx.x;     // 0..127 (output row n)
    const int i  = threadIdx.x;    // 0..255 (k)
    if (i < OUT_DIM) sWg[i] = Wg[o2 * OUT_DIM + i];
    __syncthreads();
    float acc = 0.f;
#pragma unroll 8
    for (int o = 0; o < OUT_DIM; o++)
        acc += sWg[o] * Wp[o * IN_DIM + i];
    ((__half*)g_wcf)[(i >> 6) * 8192 + o2 * 64 + (i & 63)] = __float2half_rn(acc);
}

// ---------------- CSR build ----------------
__global__ void zero_cnt_kernel(int nN) {
    int i = blockIdx.x * blockDim.x + threadIdx.x;
    if (i < nN) g_cnt[i] = 0;
}

__global__ void hist_kernel(const void* __restrict__ ei, int nE) {
    int e = blockIdx.x * blockDim.x + threadIdx.x;
    if (e >= nE) return;
    int c = load_idx(ei, (long long)nE + e, g_is64);   // col (target)
    atomicAdd(&g_cnt[c], 1);
}

__global__ void scanA_kernel(int nN) {
    __shared__ int s[256];
    int tid = threadIdx.x;
    int i = blockIdx.x * 256 + tid;
    int v = (i < nN) ? g_cnt[i] : 0;
    s[tid] = v;
    __syncthreads();
#pragma unroll
    for (int o = 1; o < 256; o <<= 1) {
        int t = (tid >= o) ? s[tid - o] : 0;
        __syncthreads();
        s[tid] += t;
        __syncthreads();
    }
    if (i < nN) g_incl[i] = s[tid];
    if (tid == 255) g_bsum[blockIdx.x] = s[255];
}

__global__ void scanB_kernel(int nb) {
    __shared__ int s[512];
    int tid = threadIdx.x;
    int v = (tid < nb) ? g_bsum[tid] : 0;
    s[tid] = v;
    __syncthreads();
#pragma unroll
    for (int o = 1; o < 512; o <<= 1) {
        int t = (tid >= o) ? s[tid - o] : 0;
        __syncthreads();
        s[tid] += t;
        __syncthreads();
    }
    if (tid < nb) g_bsum[tid] = s[tid] - v;   // exclusive
}

__global__ void scanC_kernel(int nN, int nE) {
    int i = blockIdx.x * blockDim.x + threadIdx.x;
    if (i >= nN) return;
    int incl = g_incl[i] + g_bsum[i >> 8];
    g_rowptr[i + 1] = incl;
    int cnt = g_cnt[i];
    g_cur[i] = incl - cnt;                    // exclusive offset
    g_dinv[i] = rsqrtf((float)(cnt + 1));     // +1 for self loop
    if (i == 0) g_rowptr[0] = 0;
}

__global__ void permute_kernel(const void* __restrict__ ei, int nE) {
    int e = blockIdx.x * blockDim.x + threadIdx.x;
    if (e >= nE) return;
    int is64 = g_is64;
    int r = load_idx(ei, e, is64);                     // row (source)
    int c = load_idx(ei, (long long)nE + e, is64);     // col (target)
    int p = atomicAdd(&g_cur[c], 1);
    g_srcs[p] = r;
}

// ---------------- GEMM: fp16 mma.sync + cp.async pipeline, KC=64 ---------------
// CTA tile 128(M) x 128(N), K=256 in 4 chunks of 64. 8 warps = 4(M) x 2(N).
// A: cp.async raw fp32 double buffer (cvt to half2 at fragment load).
// B: cp.async pre-converted fp16 double buffer. MMA m16n8k16.f16.
#define KC 64
#define NCHUNK (IN_DIM / KC)                 // 4
#define SROWA 68   // fp32 u32 per A smem row: 64 data + 4 pad (272B stride)
#define SROWB 36   // fp16-pair u32 per B smem row: 32 data + 4 pad (144B stride)
#define ABUF_U32 (128 * SROWA)               // 8704
#define BBUF_U32 (128 * SROWB)               // 4608
#define OFF_B0 (2 * ABUF_U32)                // 17408
#define GEMM_SMEM_BYTES ((2 * ABUF_U32 + 2 * BBUF_U32) * 4)  // 106496 B

__device__ __forceinline__ void mma_f16(float* c, const uint32_t* a, uint32_t b0, uint32_t b1) {
    asm volatile(
        "mma.sync.aligned.m16n8k16.row.col.f32.f16.f16.f32 "
        "{%0,%1,%2,%3}, {%4,%5,%6,%7}, {%8,%9}, {%0,%1,%2,%3};"
        : "+f"(c[0]), "+f"(c[1]), "+f"(c[2]), "+f"(c[3])
        : "r"(a[0]), "r"(a[1]), "r"(a[2]), "r"(a[3]), "r"(b0), "r"(b1));
}

__device__ __forceinline__ void stage_chunk(uint32_t sbase, int buf, const float* __restrict__ x,
                                            int m0, int ch, int tid, int nN) {
    const int kk = ch * KC;
    // A: 128 rows x 64 f32 = 2048 float4, 8 per thread
#pragma unroll
    for (int i = 0; i < 8; i++) {
        int idx = tid + i * 256;
        int row = idx >> 4, q = idx & 15;
        int gm  = m0 + row;
        uint32_t dA = sbase + (uint32_t)(buf * ABUF_U32 + row * SROWA + q * 4) * 4u;
        cp16(dA, x + (size_t)gm * IN_DIM + kk + q * 4, gm < nN);
    }
    // B: 128 n x 64 fp16 = 1024 uint4, 4 per thread
    const uint4* bsrc = (const uint4*)(g_wcf + ch * 4096);
#pragma unroll
    for (int i = 0; i < 4; i++) {
        int idx = tid + i * 256;
        int n = idx >> 3, q = idx & 7;
        uint32_t dB = sbase + (uint32_t)(OFF_B0 + buf * BBUF_U32 + n * SROWB + q * 4) * 4u;
        cp16(dB, bsrc + idx, true);
    }
}

__global__ void __launch_bounds__(256) gemm_mma_kernel(const float* __restrict__ x, int nN) {
    extern __shared__ uint32_t smemD[];
    uint32_t sbase = smem_u32(smemD);

    const int tid  = threadIdx.x;
    const int wid  = tid >> 5;
    const int lane = tid & 31;
    const int g    = lane >> 2;   // groupID
    const int tg   = lane & 3;    // thread in group
    const int wm   = wid >> 1;    // 0..3  -> m offset 32*wm
    const int wn   = wid & 1;     // 0..1  -> n offset 64*wn
    const int m0   = blockIdx.x * 128;

    float acc[2][8][4];
#pragma unroll
    for (int mt = 0; mt < 2; mt++)
#pragma unroll
        for (int nt = 0; nt < 8; nt++)
#pragma unroll
            for (int j = 0; j < 4; j++) acc[mt][nt][j] = 0.f;

    stage_chunk(sbase, 0, x, m0, 0, tid, nN);
    asm volatile("cp.async.commit_group;" ::: "memory");

    for (int ch = 0; ch < NCHUNK; ch++) {
        const int buf = ch & 1;
        if (ch + 1 < NCHUNK) {
            stage_chunk(sbase, buf ^ 1, x, m0, ch + 1, tid, nN);
            asm volatile("cp.async.commit_group;" ::: "memory");
            asm volatile("cp.async.wait_group 1;" ::: "memory");
        } else {
            asm volatile("cp.async.wait_group 0;" ::: "memory");
        }
        __syncthreads();

        const float*    sa = (const float*)(smemD + buf * ABUF_U32);
        const uint32_t* sb = smemD + OFF_B0 + buf * BBUF_U32;

#pragma unroll
        for (int ks = 0; ks < KC / 16; ks++) {
            const int kb = ks * 16;     // in f32 units
            uint32_t a[2][4];
#pragma unroll
            for (int mt = 0; mt < 2; mt++) {
                int r0 = (wm * 32 + mt * 16 + g) * SROWA + kb + tg * 2;
                int r1 = (wm * 32 + mt * 16 + g + 8) * SROWA + kb + tg * 2;
                float2 f0 = *(const float2*)(sa + r0);
                float2 f1 = *(const float2*)(sa + r1);
                float2 f2 = *(const float2*)(sa + r0 + 8);
                float2 f3 = *(const float2*)(sa + r1 + 8);
                a[mt][0] = h2_bits(__floats2half2_rn(f0.x, f0.y));
                a[mt][1] = h2_bits(__floats2half2_rn(f1.x, f1.y));
                a[mt][2] = h2_bits(__floats2half2_rn(f2.x, f2.y));
                a[mt][3] = h2_bits(__floats2half2_rn(f3.x, f3.y));
            }
#pragma unroll
            for (int nt = 0; nt < 8; nt++) {
                int n = wn * 64 + nt * 8 + g;
                int o = n * SROWB + ks * 8 + tg;
                uint32_t b0 = sb[o], b1 = sb[o + 4];
#pragma unroll
                for (int mt = 0; mt < 2; mt++)
                    mma_f16(acc[mt][nt], a[mt], b0, b1);
            }
        }
        __syncthreads();
    }

    // epilogue: store h (unscaled) as fp16
#pragma unroll
    for (int mt = 0; mt < 2; mt++) {
        int r0 = m0 + wm * 32 + mt * 16 + g;
        int r1 = r0 + 8;
#pragma unroll
        for (int nt = 0; nt < 8; nt++) {
            int col = wn * 64 + nt * 8 + tg * 2;
            if (r0 < nN) {
                __half2 o = __floats2half2_rn(acc[mt][nt][0], acc[mt][nt][1]);
                *(__half2*)(g_h16 + (size_t)r0 * OUT_DIM + col) = o;
            }
            if (r1 < nN) {
                __half2 o = __floats2half2_rn(acc[mt][nt][2], acc[mt][nt][3]);
                *(__half2*)(g_h16 + (size_t)r1 * OUT_DIM + col) = o;
            }
        }
    }
}

// ---------------- fused aggregate + finalize (paired-edge half-warp gather) ------
__device__ __forceinline__ void accu4(float* a, uint4 raw, float d) {
    __half2* h = (__half2*)&raw;
#pragma unroll
    for (int k = 0; k < 4; k++) {
        float2 f = __half22float2(h[k]);
        a[2 * k]     += f.x * d;
        a[2 * k + 1] += f.y * d;
    }
}

__global__ void __launch_bounds__(256) aggregate_kernel(
    float* __restrict__ out, const float* __restrict__ bg, int nN) {
    int w    = (int)((blockIdx.x * (unsigned)blockDim.x + threadIdx.x) >> 5);
    int lane = threadIdx.x & 31;
    int hl   = lane >> 4;          // half id: item parity
    int sl   = lane & 15;          // sublane: feature group 8*sl..8*sl+7
    if (w >= nN) return;

    int beg = g_rowptr[w];
    int end = g_rowptr[w + 1];
    int nItems = 1 + (end - beg);  // self + edges
    float dw = g_dinv[w];

    float a[8] = {0.f, 0.f, 0.f, 0.f, 0.f, 0.f, 0.f, 0.f};

    int j = hl;
    // batched: 8 items per half per round (16 rows in flight warp-wide)
    for (; j + 14 < nItems; j += 16) {
        int rows[8];
#pragma unroll
        for (int t = 0; t < 8; t++) {
            int jj = j + 2 * t;
            rows[t] = (jj == 0) ? w : __ldg(&g_srcs[beg + jj - 1]);
        }
        uint4 rr[8];
#pragma unroll
        for (int t = 0; t < 8; t++)
            rr[t] = __ldg((const uint4*)(g_h16 + (size_t)rows[t] * OUT_DIM) + sl);
        float dd[8];
#pragma unroll
        for (int t = 0; t < 8; t++) dd[t] = __ldg(&g_dinv[rows[t]]);
#pragma unroll
        for (int t = 0; t < 8; t++) accu4(a, rr[t], dd[t]);
    }
    for (; j < nItems; j += 2) {
        int row = (j == 0) ? w : __ldg(&g_srcs[beg + j - 1]);
        uint4 r = __ldg((const uint4*)(g_h16 + (size_t)row * OUT_DIM) + sl);
        float d = __ldg(&g_dinv[row]);
        accu4(a, r, d);
    }

#pragma unroll
    for (int k = 0; k < 8; k++) a[k] += __shfl_xor_sync(0xffffffffu, a[k], 16);

    float4 b0 = ((const float4*)bg)[sl * 2];
    float4 b1 = ((const float4*)bg)[sl * 2 + 1];
    a[0] = a[0] * dw + b0.x;  a[1] = a[1] * dw + b0.y;
    a[2] = a[2] * dw + b0.z;  a[3] = a[3] * dw + b0.w;
    a[4] = a[4] * dw + b1.x;  a[5] = a[5] * dw + b1.y;
    a[6] = a[6] * dw + b1.z;  a[7] = a[7] * dw + b1.w;

    float ss = 0.f;
#pragma unroll
    for (int k = 0; k < 8; k++) ss += a[k] * a[k];
#pragma unroll
    for (int o = 8; o > 0; o >>= 1) ss += __shfl_xor_sync(0xffffffffu, ss, o);
    float inv = 1.0f / fmaxf(sqrtf(ss), 1e-12f);

    float4 v = (hl == 0)
        ? make_float4(a[0] * inv, a[1] * inv, a[2] * inv, a[3] * inv)
        : make_float4(a[4] * inv, a[5] * inv, a[6] * inv, a[7] * inv);
    *(float4*)(out + (size_t)w * OUT_DIM + sl * 8 + hl * 4) = v;
}

// ---------------- launch (stream fork/join, capture-legal, round-10 order) -------
extern "C" void kernel_launch(void* const* d_in, const int* in_sizes, int n_in,
                              void* d_out, int out_size) {
    const float* x  = (const float*)d_in[0];
    const void*  ei = d_in[1];
    const float* Wp = (const float*)d_in[2];
    const float* Wg = (const float*)d_in[3];
    const float* bg = (const float*)d_in[4];
    float* out = (float*)d_out;

    const int nN = in_sizes[0] / IN_DIM;   // 100000
    const int nE = in_sizes[1] / 2;        // 1600000
    const int nScanBlocks = (nN + 255) / 256;

    static cudaStream_t s2;
    static cudaEvent_t evF, evJ;
    static bool inited = false;
    if (!inited) {
        cudaStreamCreateWithFlags(&s2, cudaStreamNonBlocking);
        cudaEventCreateWithFlags(&evF, cudaEventDisableTiming);
        cudaEventCreateWithFlags(&evJ, cudaEventDisableTiming);
        cudaFuncSetAttribute(gemm_mma_kernel,
                             cudaFuncAttributeMaxDynamicSharedMemorySize,
                             GEMM_SMEM_BYTES);
        inited = true;
    }

    // fork: CSR chain on s2, GEMM chain on default stream
    cudaEventRecord(evF, 0);
    cudaStreamWaitEvent(s2, evF, 0);

    detect_kernel<<<1, 32, 0, s2>>>(ei);
    zero_cnt_kernel<<<(nN + 255) / 256, 256, 0, s2>>>(nN);
    hist_kernel<<<(nE + 255) / 256, 256, 0, s2>>>(ei, nE);
    scanA_kernel<<<nScanBlocks, 256, 0, s2>>>(nN);
    scanB_kernel<<<1, 512, 0, s2>>>(nScanBlocks);
    scanC_kernel<<<(nN + 255) / 256, 256, 0, s2>>>(nN, nE);
    permute_kernel<<<(nE + 255) / 256, 256, 0, s2>>>(ei, nE);
    cudaEventRecord(evJ, s2);

    wc_kernel<<<OUT_DIM, 256>>>(Wp, Wg);
    gemm_mma_kernel<<<(nN + 127) / 128, 256, GEMM_SMEM_BYTES>>>(x, nN);

    // join
    cudaStreamWaitEvent(0, evJ, 0);

    long long agg_threads = (long long)nN * 32;
    int agg_blocks = (int)((agg_threads + 255) / 256);
    aggregate_kernel<<<agg_blocks, 256>>>(out, bg, nN);
}

// round 16
// speedup vs baseline: 1.1165x; 1.1165x over previous
#include <cuda_runtime.h>
#include <cuda_fp16.h>
#include <cstdint>
#include <cstddef>

#define N_NODES 100000
#define N_EDGES 1600000
#define IN_DIM  256
#define OUT_DIM 128

// ---------------- scratch (no cudaMalloc allowed) ----------------
__device__ __half g_h16[(size_t)N_NODES * OUT_DIM]; // h (unscaled, fp16)  (25.6 MB)
__device__ uint32_t g_wcf[16384];                   // Wc fp16, fragment-ordered per chunk
__device__ float g_dinv[N_NODES];                   // 1/sqrt(deg)
__device__ int   g_cnt[N_NODES];                    // in-degree (edges only)
__device__ int   g_cur[N_NODES];                    // scatter cursors
__device__ int   g_rowptr[N_NODES + 1];             // CSR row pointers (by target)
__device__ int   g_srcs[N_EDGES];                   // sorted-by-target source ids
__device__ int   g_incl[N_NODES];                   // per-chunk inclusive scans
__device__ int   g_bsum[512];                       // block sums for scan
__device__ int   g_is64;                            // edge_index dtype flag

__device__ __forceinline__ uint32_t smem_u32(const void* p) {
    uint32_t a;
    asm("{ .reg .u64 t; cvta.to.shared.u64 t, %1; cvt.u32.u64 %0, t; }" : "=r"(a) : "l"(p));
    return a;
}

__device__ __forceinline__ uint32_t h2_bits(__half2 h) {
    return *reinterpret_cast<uint32_t*>(&h);
}

__device__ __forceinline__ void cp16(uint32_t dst, const void* src, bool pred) {
    int sz = pred ? 16 : 0;
    asm volatile("cp.async.ca.shared.global [%0], [%1], 16, %2;"
                 :: "r"(dst), "l"(src), "r"(sz) : "memory");
}

// ---------------- dtype detection (int64 vs int32 edge_index) ----------------
__global__ void detect_kernel(const void* __restrict__ ei) {
    if (threadIdx.x == 0 && blockIdx.x == 0) {
        const long long* p = (const long long*)ei;
        int is64 = 1;
        for (int i = 0; i < 8; i++) {
            long long v = p[i];
            if (v < 0 || v >= N_NODES) { is64 = 0; break; }
        }
        g_is64 = is64;
    }
}

__device__ __forceinline__ int load_idx(const void* __restrict__ ei, long long i, int is64) {
    if (is64) return (int)((const long long*)ei)[i];
    return ((const int*)ei)[i];
}

// ---------------- Wc = Wg @ Wp, fp16 in mma-fragment order ----------------
// Per (ch, n): 32 halves. For k16 step ks, k-pair p (p=0..7), half h:
//   p<4  -> b0 of tg=p    -> u32 slot 2p
//   p>=4 -> b1 of tg=p-4  -> u32 slot 2(p-4)+1
// so a thread's (b0,b1) are adjacent u32s -> single LDS.64 in the GEMM.
__global__ void wc_kernel(const float* __restrict__ Wp, const float* __restrict__ Wg) {
    __shared__ float sWg[OUT_DIM];
    const int o2 = blockIdx.x;     // 0..127 (output row n)
    const int i  = threadIdx.x;    // 0..255 (k)
    if (i < OUT_DIM) sWg[i] = Wg[o2 * OUT_DIM + i];
    __syncthreads();
    float acc = 0.f;
#pragma unroll 8
    for (int o = 0; o < OUT_DIM; o++)
        acc += sWg[o] * Wp[o * IN_DIM + i];
    int ch   = i >> 5;
    int kloc = i & 31;
    int ks   = kloc >> 4;
    int r    = kloc & 15;
    int p    = r >> 1;
    int h    = r & 1;
    int slot = (p < 4) ? (p * 2) : ((p - 4) * 2 + 1);
    ((__half*)g_wcf)[ch * 4096 + o2 * 32 + ks * 16 + slot * 2 + h] = __float2half_rn(acc);
}

// ---------------- CSR build ----------------
__global__ void zero_cnt_kernel(int nN) {
    int i = blockIdx.x * blockDim.x + threadIdx.x;
    if (i < nN) g_cnt[i] = 0;
}

__global__ void hist_kernel(const void* __restrict__ ei, int nE) {
    int e = blockIdx.x * blockDim.x + threadIdx.x;
    if (e >= nE) return;
    int c = load_idx(ei, (long long)nE + e, g_is64);   // col (target)
    atomicAdd(&g_cnt[c], 1);
}

__global__ void scanA_kernel(int nN) {
    __shared__ int s[256];
    int tid = threadIdx.x;
    int i = blockIdx.x * 256 + tid;
    int v = (i < nN) ? g_cnt[i] : 0;
    s[tid] = v;
    __syncthreads();
#pragma unroll
    for (int o = 1; o < 256; o <<= 1) {
        int t = (tid >= o) ? s[tid - o] : 0;
        __syncthreads();
        s[tid] += t;
        __syncthreads();
    }
    if (i < nN) g_incl[i] = s[tid];
    if (tid == 255) g_bsum[blockIdx.x] = s[255];
}

__global__ void scanB_kernel(int nb) {
    __shared__ int s[512];
    int tid = threadIdx.x;
    int v = (tid < nb) ? g_bsum[tid] : 0;
    s[tid] = v;
    __syncthreads();
#pragma unroll
    for (int o = 1; o < 512; o <<= 1) {
        int t = (tid >= o) ? s[tid - o] : 0;
        __syncthreads();
        s[tid] += t;
        __syncthreads();
    }
    if (tid < nb) g_bsum[tid] = s[tid] - v;   // exclusive
}

__global__ void scanC_kernel(int nN, int nE) {
    int i = blockIdx.x * blockDim.x + threadIdx.x;
    if (i >= nN) return;
    int incl = g_incl[i] + g_bsum[i >> 8];
    g_rowptr[i + 1] = incl;
    int cnt = g_cnt[i];
    g_cur[i] = incl - cnt;                    // exclusive offset
    g_dinv[i] = rsqrtf((float)(cnt + 1));     // +1 for self loop
    if (i == 0) g_rowptr[0] = 0;
}

__global__ void permute_kernel(const void* __restrict__ ei, int nE) {
    int e = blockIdx.x * blockDim.x + threadIdx.x;
    if (e >= nE) return;
    int is64 = g_is64;
    int r = load_idx(ei, e, is64);                     // row (source)
    int c = load_idx(ei, (long long)nE + e, is64);     // col (target)
    int p = atomicAdd(&g_cur[c], 1);
    g_srcs[p] = r;
}

// ---------------- GEMM: fp16 mma.sync + cp.async pipeline, KC=32 ---------------
// CTA tile 128(M) x 128(N), K=256 in 8 chunks of 32. 8 warps = 4(M) x 2(N).
// A: cp.async raw fp32 double buffer (cvt to half2 at fragment load).
// B: cp.async fragment-ordered fp16 double buffer (single LDS.64 per fragment).
#define KC 32
#define NCHUNK (IN_DIM / KC)
#define SROWA 36   // fp32 u32 per A smem row: 32 data + 4 pad (144B stride)
#define SROWB 24   // u32 per B smem row: 16 data + 8 pad (96B, conflict-free)
#define ABUF_U32 (128 * SROWA)          // 4608
#define BBUF_U32 (128 * SROWB)          // 3072
#define OFF_B0 (2 * ABUF_U32)           // 9216
#define GEMM_SMEM_BYTES ((2 * ABUF_U32 + 2 * BBUF_U32) * 4)  // 61440 B

__device__ __forceinline__ void mma_f16(float* c, const uint32_t* a, uint32_t b0, uint32_t b1) {
    asm volatile(
        "mma.sync.aligned.m16n8k16.row.col.f32.f16.f16.f32 "
        "{%0,%1,%2,%3}, {%4,%5,%6,%7}, {%8,%9}, {%0,%1,%2,%3};"
        : "+f"(c[0]), "+f"(c[1]), "+f"(c[2]), "+f"(c[3])
        : "r"(a[0]), "r"(a[1]), "r"(a[2]), "r"(a[3]), "r"(b0), "r"(b1));
}

__device__ __forceinline__ void stage_chunk(uint32_t sbase, int buf, const float* __restrict__ x,
                                            int m0, int ch, int tid, int nN) {
    const int kk = ch * KC;
#pragma unroll
    for (int i = 0; i < 4; i++) {
        int idx = tid + i * 256;
        int row = idx >> 3, q = idx & 7;
        int gm  = m0 + row;
        uint32_t dA = sbase + (uint32_t)(buf * ABUF_U32 + row * SROWA + q * 4) * 4u;
        cp16(dA, x + (size_t)gm * IN_DIM + kk + q * 4, gm < nN);
    }
    // B: 512 uint4 per chunk (128 n x 4 x 16B)
    const uint4* bsrc = (const uint4*)(g_wcf + ch * 2048);
#pragma unroll
    for (int i = 0; i < 2; i++) {
        int idx = tid + i * 256;
        int n = idx >> 2, q = idx & 3;
        uint32_t dB = sbase + (uint32_t)(OFF_B0 + buf * BBUF_U32 + n * SROWB + q * 4) * 4u;
        cp16(dB, bsrc + idx, true);
    }
}

__global__ void __launch_bounds__(256) gemm_mma_kernel(const float* __restrict__ x, int nN) {
    extern __shared__ uint32_t smemD[];
    uint32_t sbase = smem_u32(smemD);

    const int tid  = threadIdx.x;
    const int wid  = tid >> 5;
    const int lane = tid & 31;
    const int g    = lane >> 2;   // groupID
    const int tg   = lane & 3;    // thread in group
    const int wm   = wid >> 1;    // 0..3  -> m offset 32*wm
    const int wn   = wid & 1;     // 0..1  -> n offset 64*wn
    const int m0   = blockIdx.x * 128;

    float acc[2][8][4];
#pragma unroll
    for (int mt = 0; mt < 2; mt++)
#pragma unroll
        for (int nt = 0; nt < 8; nt++)
#pragma unroll
            for (int j = 0; j < 4; j++) acc[mt][nt][j] = 0.f;

    stage_chunk(sbase, 0, x, m0, 0, tid, nN);
    asm volatile("cp.async.commit_group;" ::: "memory");

    for (int ch = 0; ch < NCHUNK; ch++) {
        const int buf = ch & 1;
        if (ch + 1 < NCHUNK) {
            stage_chunk(sbase, buf ^ 1, x, m0, ch + 1, tid, nN);
            asm volatile("cp.async.commit_group;" ::: "memory");
            asm volatile("cp.async.wait_group 1;" ::: "memory");
        } else {
            asm volatile("cp.async.wait_group 0;" ::: "memory");
        }
        __syncthreads();

        const float*    sa = (const float*)(smemD + buf * ABUF_U32);
        const uint32_t* sb = smemD + OFF_B0 + buf * BBUF_U32;

#pragma unroll
        for (int ks = 0; ks < KC / 16; ks++) {
            const int kb = ks * 16;
            uint32_t a[2][4];
#pragma unroll
            for (int mt = 0; mt < 2; mt++) {
                int r0 = (wm * 32 + mt * 16 + g) * SROWA + kb + tg * 2;
                int r1 = (wm * 32 + mt * 16 + g + 8) * SROWA + kb + tg * 2;
                float2 f0 = *(const float2*)(sa + r0);
                float2 f1 = *(const float2*)(sa + r1);
                float2 f2 = *(const float2*)(sa + r0 + 8);
                float2 f3 = *(const float2*)(sa + r1 + 8);
                a[mt][0] = h2_bits(__floats2half2_rn(f0.x, f0.y));
                a[mt][1] = h2_bits(__floats2half2_rn(f1.x, f1.y));
                a[mt][2] = h2_bits(__floats2half2_rn(f2.x, f2.y));
                a[mt][3] = h2_bits(__floats2half2_rn(f3.x, f3.y));
            }
#pragma unroll
            for (int nt = 0; nt < 8; nt++) {
                int n = wn * 64 + nt * 8 + g;
                uint2 bb = *(const uint2*)(sb + n * SROWB + ks * 8 + tg * 2);
#pragma unroll
                for (int mt = 0; mt < 2; mt++)
                    mma_f16(acc[mt][nt], a[mt], bb.x, bb.y);
            }
        }
        __syncthreads();
    }

    // epilogue: store h (unscaled) as fp16
#pragma unroll
    for (int mt = 0; mt < 2; mt++) {
        int r0 = m0 + wm * 32 + mt * 16 + g;
        int r1 = r0 + 8;
#pragma unroll
        for (int nt = 0; nt < 8; nt++) {
            int col = wn * 64 + nt * 8 + tg * 2;
            if (r0 < nN) {
                __half2 o = __floats2half2_rn(acc[mt][nt][0], acc[mt][nt][1]);
                *(__half2*)(g_h16 + (size_t)r0 * OUT_DIM + col) = o;
            }
            if (r1 < nN) {
                __half2 o = __floats2half2_rn(acc[mt][nt][2], acc[mt][nt][3]);
                *(__half2*)(g_h16 + (size_t)r1 * OUT_DIM + col) = o;
            }
        }
    }
}

// ---------------- fused aggregate + finalize (paired-edge half-warp gather) ------
__device__ __forceinline__ void accu4(float* a, uint4 raw, float d) {
    __half2* h = (__half2*)&raw;
#pragma unroll
    for (int k = 0; k < 4; k++) {
        float2 f = __half22float2(h[k]);
        a[2 * k]     += f.x * d;
        a[2 * k + 1] += f.y * d;
    }
}

__global__ void __launch_bounds__(256) aggregate_kernel(
    float* __restrict__ out, const float* __restrict__ bg, int nN) {
    int w    = (int)((blockIdx.x * (unsigned)blockDim.x + threadIdx.x) >> 5);
    int lane = threadIdx.x & 31;
    int hl   = lane >> 4;          // half id: item parity
    int sl   = lane & 15;          // sublane: feature group 8*sl..8*sl+7
    if (w >= nN) return;

    int beg = g_rowptr[w];
    int end = g_rowptr[w + 1];
    int nItems = 1 + (end - beg);  // self + edges
    float dw = g_dinv[w];

    float a[8] = {0.f, 0.f, 0.f, 0.f, 0.f, 0.f, 0.f, 0.f};

    int j = hl;
    // batched: 8 items per half per round (16 rows in flight warp-wide)
    for (; j + 14 < nItems; j += 16) {
        int rows[8];
#pragma unroll
        for (int t = 0; t < 8; t++) {
            int jj = j + 2 * t;
            rows[t] = (jj == 0) ? w : __ldg(&g_srcs[beg + jj - 1]);
        }
        uint4 rr[8];
#pragma unroll
        for (int t = 0; t < 8; t++)
            rr[t] = __ldg((const uint4*)(g_h16 + (size_t)rows[t] * OUT_DIM) + sl);
        float dd[8];
#pragma unroll
        for (int t = 0; t < 8; t++) dd[t] = __ldg(&g_dinv[rows[t]]);
#pragma unroll
        for (int t = 0; t < 8; t++) accu4(a, rr[t], dd[t]);
    }
    for (; j < nItems; j += 2) {
        int row = (j == 0) ? w : __ldg(&g_srcs[beg + j - 1]);
        uint4 r = __ldg((const uint4*)(g_h16 + (size_t)row * OUT_DIM) + sl);
        float d = __ldg(&g_dinv[row]);
        accu4(a, r, d);
    }

#pragma unroll
    for (int k = 0; k < 8; k++) a[k] += __shfl_xor_sync(0xffffffffu, a[k], 16);

    float4 b0 = ((const float4*)bg)[sl * 2];
    float4 b1 = ((const float4*)bg)[sl * 2 + 1];
    a[0] = a[0] * dw + b0.x;  a[1] = a[1] * dw + b0.y;
    a[2] = a[2] * dw + b0.z;  a[3] = a[3] * dw + b0.w;
    a[4] = a[4] * dw + b1.x;  a[5] = a[5] * dw + b1.y;
    a[6] = a[6] * dw + b1.z;  a[7] = a[7] * dw + b1.w;

    float ss = 0.f;
#pragma unroll
    for (int k = 0; k < 8; k++) ss += a[k] * a[k];
#pragma unroll
    for (int o = 8; o > 0; o >>= 1) ss += __shfl_xor_sync(0xffffffffu, ss, o);
    float inv = 1.0f / fmaxf(sqrtf(ss), 1e-12f);

    float4 v = (hl == 0)
        ? make_float4(a[0] * inv, a[1] * inv, a[2] * inv, a[3] * inv)
        : make_float4(a[4] * inv, a[5] * inv, a[6] * inv, a[7] * inv);
    *(float4*)(out + (size_t)w * OUT_DIM + sl * 8 + hl * 4) = v;
}

// ---------------- launch (stream fork/join, capture-legal, round-10 order) -------
extern "C" void kernel_launch(void* const* d_in, const int* in_sizes, int n_in,
                              void* d_out, int out_size) {
    const float* x  = (const float*)d_in[0];
    const void*  ei = d_in[1];
    const float* Wp = (const float*)d_in[2];
    const float* Wg = (const float*)d_in[3];
    const float* bg = (const float*)d_in[4];
    float* out = (float*)d_out;

    const int nN = in_sizes[0] / IN_DIM;   // 100000
    const int nE = in_sizes[1] / 2;        // 1600000
    const int nScanBlocks = (nN + 255) / 256;

    static cudaStream_t s2;
    static cudaEvent_t evF, evJ;
    static bool inited = false;
    if (!inited) {
        cudaStreamCreateWithFlags(&s2, cudaStreamNonBlocking);
        cudaEventCreateWithFlags(&evF, cudaEventDisableTiming);
        cudaEventCreateWithFlags(&evJ, cudaEventDisableTiming);
        cudaFuncSetAttribute(gemm_mma_kernel,
                             cudaFuncAttributeMaxDynamicSharedMemorySize,
                             GEMM_SMEM_BYTES);
        inited = true;
    }

    // fork: CSR chain on s2, GEMM chain on default stream
    cudaEventRecord(evF, 0);
    cudaStreamWaitEvent(s2, evF, 0);

    detect_kernel<<<1, 32, 0, s2>>>(ei);
    zero_cnt_kernel<<<(nN + 255) / 256, 256, 0, s2>>>(nN);
    hist_kernel<<<(nE + 255) / 256, 256, 0, s2>>>(ei, nE);
    scanA_kernel<<<nScanBlocks, 256, 0, s2>>>(nN);
    scanB_kernel<<<1, 512, 0, s2>>>(nScanBlocks);
    scanC_kernel<<<(nN + 255) / 256, 256, 0, s2>>>(nN, nE);
    permute_kernel<<<(nE + 255) / 256, 256, 0, s2>>>(ei, nE);
    cudaEventRecord(evJ, s2);

    wc_kernel<<<OUT_DIM, 256>>>(Wp, Wg);
    gemm_mma_kernel<<<(nN + 127) / 128, 256, GEMM_SMEM_BYTES>>>(x, nN);

    // join
    cudaStreamWaitEvent(0, evJ, 0);

    long long agg_threads = (long long)nN * 32;
    int agg_blocks = (int)((agg_threads + 255) / 256);
    aggregate_kernel<<<agg_blocks, 256>>>(out, bg, nN);
}